// round 8
// baseline (speedup 1.0000x reference)
#include <cuda_runtime.h>
#include <math.h>

#define L_DIM 16384
#define Q_DIM (L_DIM / 4)          // 4096 float4 per row
#define B_DIM 64
#define K_DIM 16
#define N_ROWS 1024
#define SEGS 4                     // segments per row
#define SEG_Q (Q_DIM / SEGS)       // 1024 float4 per segment
#define ROW_BLOCKS (N_ROWS * SEGS) // 4096
#define MASK_BLOCKS (B_DIM * SEGS) // 256
#define TOTAL1 (ROW_BLOCKS + MASK_BLOCKS)
#define T1 128
#define QPT 8                      // quads per thread (T1*QPT == SEG_Q)
#define THR_FIXED 2.25f            // fixed speculative threshold (N(0,1) logits)
#define CAP_G 512

// ---- scratch (__device__ globals; statically zero-initialized) ----
__device__ unsigned int g_rowmax[N_ROWS];       // monotone float keys; atomicMax idempotent across replays
__device__ int          g_cnt[N_ROWS];          // reset by kernel 2 each launch
__device__ float        g_cval[N_ROWS][CAP_G];
__device__ int          g_cidx[N_ROWS][CAP_G];
__device__ float        g_nmask_part[B_DIM][16];
__device__ float        g_row_loss[N_ROWS];

__device__ __forceinline__ unsigned int fkey(float f) {
    unsigned int b = __float_as_uint(f);
    return b ^ ((b & 0x80000000u) ? 0xFFFFFFFFu : 0x80000000u);
}
__device__ __forceinline__ float funkey(unsigned int k) {
    unsigned int b = k ^ ((k & 0x80000000u) ? 0x80000000u : 0xFFFFFFFFu);
    return __uint_as_float(b);
}

// ---------------------------------------------------------------------------
// Kernel 1: pure streaming. NO block barriers, NO fences. Warps independent.
// ---------------------------------------------------------------------------
__global__ void __launch_bounds__(T1, 8) stream_kernel(
    const float* __restrict__ logits, const float* __restrict__ mask)
{
    const int blk  = blockIdx.x;
    const int tid  = threadIdx.x;
    const int lane = tid & 31, warp = tid >> 5;

    if (blk < ROW_BLOCKS) {
        const int row = blk >> 2, seg = blk & 3;
        const float4* z4 = (const float4*)logits + (size_t)row * Q_DIM + seg * SEG_Q;

        // front-batched burst of 8 independent LDG.128
        float4 v[QPT];
        #pragma unroll
        for (int j = 0; j < QPT; j++) v[j] = z4[tid + j * T1];

        float m = -3.4e38f;
        unsigned int qm = 0u;
        #pragma unroll
        for (int j = 0; j < QPT; j++) {
            float vm = fmaxf(fmaxf(v[j].x, v[j].y), fmaxf(v[j].z, v[j].w));
            m = fmaxf(m, vm);
            qm |= (vm > THR_FIXED ? 1u : 0u) << j;
        }
        #pragma unroll
        for (int o = 16; o; o >>= 1) m = fmaxf(m, __shfl_xor_sync(0xffffffffu, m, o));
        if (lane == 0) atomicMax(&g_rowmax[row], fkey(m));

        // push flagged candidates (L1-hot reloads; ~5% of quads flagged)
        while (qm) {
            int j = __ffs(qm) - 1;
            qm &= qm - 1u;
            int qi = tid + j * T1;                  // float4 index within segment
            float4 q = z4[qi];
            int base = (seg * SEG_Q + qi) * 4;      // element index within row
            if (q.x > THR_FIXED) { int p = atomicAdd(&g_cnt[row], 1); if (p < CAP_G) { g_cval[row][p] = q.x; g_cidx[row][p] = base + 0; } }
            if (q.y > THR_FIXED) { int p = atomicAdd(&g_cnt[row], 1); if (p < CAP_G) { g_cval[row][p] = q.y; g_cidx[row][p] = base + 1; } }
            if (q.z > THR_FIXED) { int p = atomicAdd(&g_cnt[row], 1); if (p < CAP_G) { g_cval[row][p] = q.z; g_cidx[row][p] = base + 2; } }
            if (q.w > THR_FIXED) { int p = atomicAdd(&g_cnt[row], 1); if (p < CAP_G) { g_cval[row][p] = q.w; g_cidx[row][p] = base + 3; } }
        }
    } else {
        // mask quarter-row block: per-warp partial sums, no block reduce
        const int mb = blk - ROW_BLOCKS;
        const int b = mb >> 2, seg = mb & 3;
        const float4* m4 = (const float4*)mask + (size_t)b * Q_DIM + seg * SEG_Q;
        float4 v[QPT];
        #pragma unroll
        for (int j = 0; j < QPT; j++) v[j] = m4[tid + j * T1];
        float s = 0.f;
        #pragma unroll
        for (int j = 0; j < QPT; j++) s += (v[j].x + v[j].y) + (v[j].z + v[j].w);
        #pragma unroll
        for (int o = 16; o; o >>= 1) s += __shfl_xor_sync(0xffffffffu, s, o);
        if (lane == 0) g_nmask_part[b][seg * 4 + warp] = s;
    }
}

// ---------------------------------------------------------------------------
// Kernel 2: one warp per row — Michelot tau + loss terms; resets counters.
// ---------------------------------------------------------------------------
__global__ void __launch_bounds__(128) solve_kernel(
    const float* __restrict__ logits, const float* __restrict__ mask)
{
    const int row  = blockIdx.x * 4 + (threadIdx.x >> 5);
    const int lane = threadIdx.x & 31;
    const int b    = row >> 4;

    const float mx  = funkey(g_rowmax[row]);
    const float thr = mx - 1.0f;               // support ⊆ {z > max-1}
    int cnt = g_cnt[row];

    if (thr < THR_FIXED || cnt > CAP_G) {
        // fallback (≈never): re-gather this row at thr
        if (lane == 0) g_cnt[row] = 0;
        __syncwarp();
        const float4* z4 = (const float4*)logits + (size_t)row * Q_DIM;
        for (int i = lane; i < Q_DIM; i += 32) {
            float4 q = z4[i];
            if (q.x > thr) { int p = atomicAdd(&g_cnt[row], 1); if (p < CAP_G) { g_cval[row][p] = q.x; g_cidx[row][p] = 4 * i + 0; } }
            if (q.y > thr) { int p = atomicAdd(&g_cnt[row], 1); if (p < CAP_G) { g_cval[row][p] = q.y; g_cidx[row][p] = 4 * i + 1; } }
            if (q.z > thr) { int p = atomicAdd(&g_cnt[row], 1); if (p < CAP_G) { g_cval[row][p] = q.z; g_cidx[row][p] = 4 * i + 2; } }
            if (q.w > thr) { int p = atomicAdd(&g_cnt[row], 1); if (p < CAP_G) { g_cval[row][p] = q.w; g_cidx[row][p] = 4 * i + 3; } }
        }
        __syncwarp();
        cnt = atomicAdd(&g_cnt[row], 0);
    }
    cnt = min(cnt, CAP_G);

    // Michelot from tau0 = max-1 (valid lower bound on tau*)
    float tau = thr;
    for (int iter = 0; iter < 64; iter++) {
        float s = 0.f; int c = 0;
        for (int i = lane; i < cnt; i += 32) {
            float v = g_cval[row][i];
            if (v > tau) { s += v; c++; }
        }
        #pragma unroll
        for (int o = 16; o; o >>= 1) {
            s += __shfl_xor_sync(0xffffffffu, s, o);
            c += __shfl_xor_sync(0xffffffffu, c, o);
        }
        float nt = (s - 1.0f) / (float)c;       // c >= 1 (argmax always active)
        if (nt == tau) break;
        tau = nt;
    }

    // mask row sum from the 16 warp partials
    float ns = (lane < 16) ? g_nmask_part[b][lane] : 0.f;
    #pragma unroll
    for (int o = 16; o; o >>= 1) ns += __shfl_xor_sync(0xffffffffu, ns, o);
    const float inv_n = 1.0f / fmaxf(ns, 1e-12f);

    const float* mrow = mask + (size_t)b * L_DIM;
    float sp2 = 0.f, spm = 0.f;
    for (int i = lane; i < cnt; i += 32) {
        float p = g_cval[row][i] - tau;
        if (p > 0.f) {
            sp2 += p * p;
            spm += mrow[g_cidx[row][i]] * p;    // mask is 0/1
        }
    }
    #pragma unroll
    for (int o = 16; o; o >>= 1) {
        sp2 += __shfl_xor_sync(0xffffffffu, sp2, o);
        spm += __shfl_xor_sync(0xffffffffu, spm, o);
    }
    if (lane == 0) {
        // sum_L (p-q)^2 = sum p^2 - 2*inv_n*spm + 1/n
        g_row_loss[row] = 0.5f * sp2 - inv_n * spm + 0.5f * inv_n;
        g_cnt[row] = 0;                         // reset for next graph replay
    }
}

// ---------------------------------------------------------------------------
// Kernel 3: deterministic 1024 -> 1 reduction
// ---------------------------------------------------------------------------
__global__ void reduce_kernel(float* __restrict__ out) {
    __shared__ float sh[512];
    int tid = threadIdx.x;
    sh[tid] = g_row_loss[tid] + g_row_loss[tid + 512];
    __syncthreads();
    #pragma unroll
    for (int o = 256; o > 0; o >>= 1) {
        if (tid < o) sh[tid] += sh[tid + o];
        __syncthreads();
    }
    if (tid == 0) out[0] = sh[0] * (1.0f / (float)N_ROWS);
}

// ---------------------------------------------------------------------------
extern "C" void kernel_launch(void* const* d_in, const int* in_sizes, int n_in,
                              void* d_out, int out_size) {
    const float* logits = (const float*)d_in[0];   // (64,16,16384) fp32
    const float* mask   = (const float*)d_in[1];   // (64,16384) fp32
    float* out = (float*)d_out;

    stream_kernel<<<TOTAL1, T1>>>(logits, mask);
    solve_kernel<<<N_ROWS / 4, 128>>>(logits, mask);
    reduce_kernel<<<1, 512>>>(out);
}

// round 9
// speedup vs baseline: 1.4431x; 1.4431x over previous
#include <cuda_runtime.h>
#include <math.h>

#define L_DIM 16384
#define Q_DIM (L_DIM / 4)
#define B_DIM 64
#define K_DIM 16
#define N_ROWS 1024
#define MASK_BLOCKS B_DIM
#define TOTAL_BLOCKS (N_ROWS + MASK_BLOCKS)   // 1088
#define THREADS 256
#define ITERS 16                   // quads per thread (256*16 = 4096 = row)
#define DEPTH 4                    // pipeline depth (float4 loads in flight)
#define GROUPS (ITERS / DEPTH)     // 4
#define CAP 1024
#define THR_FIXED 2.0f             // speculative flag threshold (N(0,1) logits)

// Scratch (allocation-free rule: __device__ globals)
__device__ float g_nmask[B_DIM];
__device__ float g_sp2[N_ROWS];
__device__ float g_spm[N_ROWS];
__device__ unsigned int g_done = 0;

__global__ void __launch_bounds__(THREADS, 4) fused_kernel(
    const float* __restrict__ logits,
    const float* __restrict__ mask,
    float* __restrict__ out)
{
    __shared__ float sval[CAP];
    __shared__ int   sidx[CAP];
    __shared__ int   s_cnt;
    __shared__ float s_red[THREADS / 32];
    __shared__ float s_max;
    __shared__ float s_fin[THREADS];
    __shared__ unsigned int s_ticket;

    const int blk  = blockIdx.x;
    const int tid  = threadIdx.x;
    const int warp = tid >> 5, lane = tid & 31;

    if (blk >= N_ROWS) {
        // --------- mask-sum block (one per batch row), pipelined ----------
        const int b = blk - N_ROWS;
        const float4* m4 = (const float4*)(mask + (size_t)b * L_DIM);
        float4 a[DEPTH], nb[DEPTH];
        #pragma unroll
        for (int k = 0; k < DEPTH; k++) a[k] = m4[tid + k * THREADS];
        float s = 0.f;
        #pragma unroll
        for (int g = 0; g < GROUPS; g++) {
            if (g + 1 < GROUPS) {
                #pragma unroll
                for (int k = 0; k < DEPTH; k++) nb[k] = m4[tid + ((g + 1) * DEPTH + k) * THREADS];
            }
            #pragma unroll
            for (int k = 0; k < DEPTH; k++) s += (a[k].x + a[k].y) + (a[k].z + a[k].w);
            #pragma unroll
            for (int k = 0; k < DEPTH; k++) a[k] = nb[k];
        }
        #pragma unroll
        for (int o = 16; o; o >>= 1) s += __shfl_xor_sync(0xffffffffu, s, o);
        if (lane == 0) s_red[warp] = s;
        __syncthreads();
        if (tid == 0) {
            float t = 0.f;
            #pragma unroll
            for (int w = 0; w < THREADS / 32; w++) t += s_red[w];
            g_nmask[b] = t;
        }
    } else {
        // ----------------------- row block (b,k) ---------------------------
        const int row = blk;
        const float4* z4 = (const float4*)(logits + (size_t)row * L_DIM);
        if (tid == 0) s_cnt = 0;   // no barrier needed: next barrier is the max reduce

        // ---- pass 1: pipelined stream — next DEPTH loads always in flight ----
        float4 a[DEPTH], nb[DEPTH];
        #pragma unroll
        for (int k = 0; k < DEPTH; k++) a[k] = z4[tid + k * THREADS];
        float m = -3.4e38f;
        unsigned int qmask = 0u;
        #pragma unroll
        for (int g = 0; g < GROUPS; g++) {
            if (g + 1 < GROUPS) {
                #pragma unroll
                for (int k = 0; k < DEPTH; k++) nb[k] = z4[tid + ((g + 1) * DEPTH + k) * THREADS];
            }
            #pragma unroll
            for (int k = 0; k < DEPTH; k++) {
                float vm = fmaxf(fmaxf(a[k].x, a[k].y), fmaxf(a[k].z, a[k].w));
                m = fmaxf(m, vm);
                qmask |= (vm > THR_FIXED ? 1u : 0u) << (g * DEPTH + k);
            }
            #pragma unroll
            for (int k = 0; k < DEPTH; k++) a[k] = nb[k];
        }
        #pragma unroll
        for (int o = 16; o; o >>= 1) m = fmaxf(m, __shfl_xor_sync(0xffffffffu, m, o));
        if (lane == 0) s_red[warp] = m;
        __syncthreads();
        if (tid == 0) {
            float t = s_red[0];
            #pragma unroll
            for (int w = 1; w < THREADS / 32; w++) t = fmaxf(t, s_red[w]);
            s_max = t;
        }
        __syncthreads();
        const float supp_thr = s_max - 1.0f;   // support ⊆ {z > max-1}

        if (supp_thr >= THR_FIXED) {
            // ---- pass 2 (fast path): revisit only flagged quads (L1-hot) ----
            unsigned int qm = qmask;
            while (qm) {
                int j = __ffs(qm) - 1;
                qm &= qm - 1u;
                int i = tid + j * THREADS;
                float4 q = z4[i];
                if (q.x > supp_thr) { int p = atomicAdd(&s_cnt, 1); if (p < CAP) { sval[p] = q.x; sidx[p] = 4 * i + 0; } }
                if (q.y > supp_thr) { int p = atomicAdd(&s_cnt, 1); if (p < CAP) { sval[p] = q.y; sidx[p] = 4 * i + 1; } }
                if (q.z > supp_thr) { int p = atomicAdd(&s_cnt, 1); if (p < CAP) { sval[p] = q.z; sidx[p] = 4 * i + 2; } }
                if (q.w > supp_thr) { int p = atomicAdd(&s_cnt, 1); if (p < CAP) { sval[p] = q.w; sidx[p] = 4 * i + 3; } }
            }
            __syncthreads();
        }
        if (supp_thr < THR_FIXED || s_cnt >= CAP) {
            // ---- fallback (≈never): full re-gather from L2 at supp_thr ----
            __syncthreads();
            if (tid == 0) s_cnt = 0;
            __syncthreads();
            #pragma unroll 4
            for (int it = 0; it < ITERS; it++) {
                int i = tid + it * THREADS;
                float4 q = z4[i];
                if (q.x > supp_thr) { int p = atomicAdd(&s_cnt, 1); if (p < CAP) { sval[p] = q.x; sidx[p] = 4 * i + 0; } }
                if (q.y > supp_thr) { int p = atomicAdd(&s_cnt, 1); if (p < CAP) { sval[p] = q.y; sidx[p] = 4 * i + 1; } }
                if (q.z > supp_thr) { int p = atomicAdd(&s_cnt, 1); if (p < CAP) { sval[p] = q.z; sidx[p] = 4 * i + 2; } }
                if (q.w > supp_thr) { int p = atomicAdd(&s_cnt, 1); if (p < CAP) { sval[p] = q.w; sidx[p] = 4 * i + 3; } }
            }
            __syncthreads();
        }
        const int cnt = min(s_cnt, CAP);

        // ---- warp 0: Michelot iteration (start at tau = max-1), loss terms ----
        if (warp == 0) {
            float tau = supp_thr;   // tau* >= max-1; candidate set ⊇ support, nonempty
            for (int iter = 0; iter < 64; iter++) {
                float s = 0.f; int c = 0;
                for (int i = lane; i < cnt; i += 32) {
                    float vv = sval[i];
                    if (vv > tau) { s += vv; c++; }
                }
                #pragma unroll
                for (int o = 16; o; o >>= 1) {
                    s += __shfl_xor_sync(0xffffffffu, s, o);
                    c += __shfl_xor_sync(0xffffffffu, c, o);
                }
                float nt = (s - 1.0f) / (float)c;
                if (nt == tau) break;
                tau = nt;
            }

            const int b = row >> 4;
            const float* mrow = mask + (size_t)b * L_DIM;
            float sp2 = 0.f, spm = 0.f;
            for (int i = lane; i < cnt; i += 32) {
                float p = sval[i] - tau;
                if (p > 0.f) {
                    sp2 += p * p;
                    spm += mrow[sidx[i]] * p;   // mask is 0/1; inv_n applied at the end
                }
            }
            #pragma unroll
            for (int o = 16; o; o >>= 1) {
                sp2 += __shfl_xor_sync(0xffffffffu, sp2, o);
                spm += __shfl_xor_sync(0xffffffffu, spm, o);
            }
            if (lane == 0) {
                g_sp2[row] = sp2;
                g_spm[row] = spm;
            }
        }
    }

    // ------------- last-block-done final reduction (deterministic) ---------
    __syncthreads();
    __threadfence();
    if (tid == 0) s_ticket = atomicAdd(&g_done, 1u);
    __syncthreads();
    if (s_ticket == TOTAL_BLOCKS - 1) {
        float acc = 0.f;
        #pragma unroll
        for (int j = 0; j < N_ROWS / THREADS; j++) {
            int r = tid + j * THREADS;
            int b = r >> 4;
            float inv_n = 1.0f / fmaxf(g_nmask[b], 1e-12f);
            acc += 0.5f * g_sp2[r] - inv_n * g_spm[r] + 0.5f * inv_n;
        }
        s_fin[tid] = acc;
        __syncthreads();
        #pragma unroll
        for (int o = THREADS / 2; o > 0; o >>= 1) {
            if (tid < o) s_fin[tid] += s_fin[tid + o];
            __syncthreads();
        }
        if (tid == 0) {
            out[0] = s_fin[0] * (1.0f / (float)N_ROWS);
            g_done = 0;        // reset for next graph replay
        }
    }
}

// ---------------------------------------------------------------------------
extern "C" void kernel_launch(void* const* d_in, const int* in_sizes, int n_in,
                              void* d_out, int out_size) {
    const float* logits = (const float*)d_in[0];   // (64,16,16384) fp32
    const float* mask   = (const float*)d_in[1];   // (64,16384) fp32
    float* out = (float*)d_out;

    fused_kernel<<<TOTAL_BLOCKS, THREADS>>>(logits, mask, out);
}